// round 2
// baseline (speedup 1.0000x reference)
#include <cuda_runtime.h>
#include <cuda_bf16.h>
#include <cstdint>

#define NN   4096
#define FIN  256
#define FOUT 256
#define NH   4
#define DD   64
#define ALPHA 0.2f

// ---------------- device scratch (no allocs allowed) ----------------
__device__ float    g_h [NN * FOUT];    // x@W, fp32 exact
__device__ float    g_hr[NN * FOUT];    // tf32-rounded copy (B operand)
__device__ unsigned g_adjbits[NN * (NN / 32)];   // 2 MB bitmask
__device__ float    g_A[NH * NN];       // exp(si)
__device__ float    g_B[NH * NN];       // exp(alpha*si)
__device__ float    g_T[NH * NN];       // exp(-si)  (threshold in exp-domain)
__device__ float2   g_e12[NH * NN];     // {exp(sj), exp(alpha*sj)}
__device__ float    g_att[NN * FOUT];   // attention output pre-LN

// ---------------- kernel 1: pack adj int32 -> bits ----------------
__global__ void pack_adj_kernel(const int* __restrict__ adj) {
    int lane = threadIdx.x & 31;
    size_t gw = (size_t)(blockIdx.x * blockDim.x + threadIdx.x) >> 5;   // global warp id
    const int* base = adj + gw * 1024;
    unsigned myword = 0;
#pragma unroll
    for (int i = 0; i < 32; i++) {
        int v = base[i * 32 + lane];
        unsigned b = __ballot_sync(0xffffffffu, v > 0);
        if (lane == i) myword = b;
    }
    g_adjbits[gw * 32 + lane] = myword;
}

// ---------------- kernel 2: h = x @ W (fp32 SIMT tiled) ----------------
__global__ __launch_bounds__(256) void gemm_h_kernel(const float* __restrict__ x,
                                                     const float* __restrict__ W) {
    __shared__ float xsT[16][68];   // [k][row]
    __shared__ float wsm[16][68];   // [k][col]
    int t  = threadIdx.x;
    int m0 = blockIdx.x * 64;
    int n0 = blockIdx.y * 64;
    int r0 = (t >> 4) << 2;
    int c0 = (t & 15) << 2;
    float acc[4][4] = {};

    for (int kt = 0; kt < 16; kt++) {
        int k0 = kt * 16;
        {   // x tile 64x16, transposed store
            int row = t >> 2, c4 = t & 3;
            float4 v = *(const float4*)(x + (size_t)(m0 + row) * FIN + k0 + c4 * 4);
            xsT[c4 * 4 + 0][row] = v.x;
            xsT[c4 * 4 + 1][row] = v.y;
            xsT[c4 * 4 + 2][row] = v.z;
            xsT[c4 * 4 + 3][row] = v.w;
        }
        {   // W tile 16x64
            int r = t >> 4, c4 = t & 15;
            *(float4*)&wsm[r][c4 * 4] =
                *(const float4*)(W + (size_t)(k0 + r) * FOUT + n0 + c4 * 4);
        }
        __syncthreads();
#pragma unroll
        for (int k = 0; k < 16; k++) {
            float4 av = *(float4*)&xsT[k][r0];
            float4 bv = *(float4*)&wsm[k][c0];
            acc[0][0] += av.x * bv.x; acc[0][1] += av.x * bv.y; acc[0][2] += av.x * bv.z; acc[0][3] += av.x * bv.w;
            acc[1][0] += av.y * bv.x; acc[1][1] += av.y * bv.y; acc[1][2] += av.y * bv.z; acc[1][3] += av.y * bv.w;
            acc[2][0] += av.z * bv.x; acc[2][1] += av.z * bv.y; acc[2][2] += av.z * bv.z; acc[2][3] += av.z * bv.w;
            acc[3][0] += av.w * bv.x; acc[3][1] += av.w * bv.y; acc[3][2] += av.w * bv.z; acc[3][3] += av.w * bv.w;
        }
        __syncthreads();
    }
#pragma unroll
    for (int i = 0; i < 4; i++) {
        size_t off = (size_t)(m0 + r0 + i) * FOUT + n0 + c0;
        float4 v = make_float4(acc[i][0], acc[i][1], acc[i][2], acc[i][3]);
        *(float4*)(g_h + off) = v;
        float4 vr;
        unsigned u;
        asm("cvt.rna.tf32.f32 %0, %1;" : "=r"(u) : "f"(v.x)); vr.x = __uint_as_float(u);
        asm("cvt.rna.tf32.f32 %0, %1;" : "=r"(u) : "f"(v.y)); vr.y = __uint_as_float(u);
        asm("cvt.rna.tf32.f32 %0, %1;" : "=r"(u) : "f"(v.z)); vr.z = __uint_as_float(u);
        asm("cvt.rna.tf32.f32 %0, %1;" : "=r"(u) : "f"(v.w)); vr.w = __uint_as_float(u);
        *(float4*)(g_hr + off) = vr;
    }
}

// ---------------- kernel 3: si/sj dots + exp tables ----------------
__global__ void prep_kernel(const float* __restrict__ a) {
    __shared__ float a_s[128];
    int t = threadIdx.x;
    if (t < 128) a_s[t] = a[t];
    __syncthreads();
    int wid  = t >> 5, lane = t & 31;
    int n    = blockIdx.x * 8 + wid;
    int head = lane >> 3;
    int sub  = lane & 7;
    const float4* hrow = (const float4*)(g_h + (size_t)n * FOUT);
    float psi = 0.f, psj = 0.f;
#pragma unroll
    for (int v = 0; v < 2; v++) {
        float4 hv = hrow[lane * 2 + v];
        int db = sub * 8 + v * 4;   // d within head
        psi += hv.x * a_s[db]     + hv.y * a_s[db + 1] + hv.z * a_s[db + 2] + hv.w * a_s[db + 3];
        psj += hv.x * a_s[64 + db] + hv.y * a_s[64 + db + 1] + hv.z * a_s[64 + db + 2] + hv.w * a_s[64 + db + 3];
    }
#pragma unroll
    for (int off = 4; off; off >>= 1) {
        psi += __shfl_down_sync(0xffffffffu, psi, off);
        psj += __shfl_down_sync(0xffffffffu, psj, off);
    }
    if (sub == 0) {
        int idx = head * NN + n;
        g_A[idx]   = expf(psi);
        g_B[idx]   = expf(ALPHA * psi);
        g_T[idx]   = expf(-psi);
        g_e12[idx] = make_float2(expf(psj), expf(ALPHA * psj));
    }
}

// ---------------- kernel 4: fused attention (tf32 mma.sync) ----------------
__device__ __forceinline__ void mma_tf32(float* d, unsigned a0, unsigned a1, unsigned a2,
                                         unsigned a3, unsigned b0, unsigned b1) {
    asm volatile(
        "mma.sync.aligned.m16n8k8.row.col.f32.tf32.tf32.f32 "
        "{%0,%1,%2,%3}, {%4,%5,%6,%7}, {%8,%9}, {%0,%1,%2,%3};\n"
        : "+f"(d[0]), "+f"(d[1]), "+f"(d[2]), "+f"(d[3])
        : "r"(a0), "r"(a1), "r"(a2), "r"(a3), "r"(b0), "r"(b1));
}

// block: 64 n-rows x 1 head, loops all m in tiles of 128.  grid (64, 4), 256 thr.
__global__ __launch_bounds__(256, 2) void attn_kernel() {
    extern __shared__ float sm[];
    float*    Hs   = sm;                           // [128][72] h tile   (tf32)
    float*    Ws   = sm + 9216;                    // [128][72] w tile [m][n] (tf32)
    float2*   e12t = (float2*)(sm + 18432);        // 128
    unsigned* adjt = (unsigned*)(sm + 18688);      // 256 words
    float*    As   = sm + 18944;                   // 64
    float*    Bs   = sm + 19008;
    float*    Ts   = sm + 19072;
    float*    Sp   = sm + 19136;                   // 256
    float*    Ssm  = sm + 19392;                   // 64

    int t  = threadIdx.x;
    int hd = blockIdx.y;
    int n0 = blockIdx.x * 64;

    if (t < 64) {
        As[t] = g_A[hd * NN + n0 + t];
        Bs[t] = g_B[hd * NN + n0 + t];
        Ts[t] = g_T[hd * NN + n0 + t];
    }
    __syncthreads();

    int nl = t & 63, mc = t >> 6;
    float An = As[nl], Bn = Bs[nl], Tn = Ts[nl];
    float sacc = 0.f;

    int lane = t & 31, wid = t >> 5;
    int g = lane >> 2, tig = lane & 3;
    int wn0 = (wid & 3) * 16;       // warp n offset
    int wd0 = (wid >> 2) * 32;      // warp d offset
    float acc[4][4] = {};

    for (int mt = 0; mt < NN / 128; mt++) {
        int m0 = mt * 128;
        __syncthreads();   // previous mma reads done
        // stage h tile (tf32-rounded), 128 x 64 -> stride 72
        for (int li = t; li < 128 * 16; li += 256) {
            int mi = li >> 4, d4 = li & 15;
            float4 v = *(const float4*)(g_hr + (size_t)(m0 + mi) * FOUT + hd * DD + d4 * 4);
            *(float4*)&Hs[mi * 72 + d4 * 4] = v;
        }
        if (t < 128) e12t[t] = g_e12[hd * NN + m0 + t];
        {
            int rr = t >> 2, ww = t & 3;
            adjt[t] = g_adjbits[(size_t)(n0 + rr) * (NN / 32) + mt * 4 + ww];
        }
        __syncthreads();

        // generate w tile: thread covers (n=nl, m = mc*32 + i)
        unsigned word = adjt[nl * 4 + mc];
#pragma unroll
        for (int i = 0; i < 32; i++) {
            float2 e = e12t[mc * 32 + i];
            float wv = (e.x > Tn) ? (An * e.x) : (Bn * e.y);
            if (!(word & (1u << i))) wv = 0.f;
            sacc += wv;
            unsigned wt;
            asm("cvt.rna.tf32.f32 %0, %1;" : "=r"(wt) : "f"(wv));
            Ws[(mc * 32 + i) * 72 + nl] = __uint_as_float(wt);
        }
        __syncthreads();

        // mma: C(64x64) += W(64n x 128m) * H(128m x 64d), K=128 -> 16 k8 steps
#pragma unroll
        for (int ks = 0; ks < 16; ks++) {
            int k0 = ks * 8;
            unsigned a0 = __float_as_uint(Ws[(k0 + tig) * 72 + wn0 + g]);
            unsigned a1 = __float_as_uint(Ws[(k0 + tig) * 72 + wn0 + g + 8]);
            unsigned a2 = __float_as_uint(Ws[(k0 + tig + 4) * 72 + wn0 + g]);
            unsigned a3 = __float_as_uint(Ws[(k0 + tig + 4) * 72 + wn0 + g + 8]);
#pragma unroll
            for (int j = 0; j < 4; j++) {
                unsigned b0 = __float_as_uint(Hs[(k0 + tig) * 72 + wd0 + 8 * j + g]);
                unsigned b1 = __float_as_uint(Hs[(k0 + tig + 4) * 72 + wd0 + 8 * j + g]);
                mma_tf32(acc[j], a0, a1, a2, a3, b0, b1);
            }
        }
    }

    // softmax denominator reduction
    Sp[t] = sacc;
    __syncthreads();
    if (t < 64) Ssm[t] = Sp[t] + Sp[64 + t] + Sp[128 + t] + Sp[192 + t];
    __syncthreads();

    float inv0 = 1.0f / Ssm[wn0 + g];
    float inv1 = 1.0f / Ssm[wn0 + g + 8];
    int na = n0 + wn0 + g, nb = na + 8;
    int colbase = hd * DD + wd0 + 2 * tig;
#pragma unroll
    for (int j = 0; j < 4; j++) {
        int col = colbase + 8 * j;
        g_att[(size_t)na * FOUT + col]     = acc[j][0] * inv0;
        g_att[(size_t)na * FOUT + col + 1] = acc[j][1] * inv0;
        g_att[(size_t)nb * FOUT + col]     = acc[j][2] * inv1;
        g_att[(size_t)nb * FOUT + col + 1] = acc[j][3] * inv1;
    }
}

// ---------------- kernel 5: LayerNorm ----------------
__global__ void ln_kernel(const float* __restrict__ gamma,
                          const float* __restrict__ beta,
                          float* __restrict__ out) {
    int wid = threadIdx.x >> 5, lane = threadIdx.x & 31;
    int n = blockIdx.x * 8 + wid;
    const float4* row = (const float4*)(g_att + (size_t)n * FOUT);
    float4 v0 = row[lane * 2], v1 = row[lane * 2 + 1];
    float s = v0.x + v0.y + v0.z + v0.w + v1.x + v1.y + v1.z + v1.w;
#pragma unroll
    for (int o = 16; o; o >>= 1) s += __shfl_xor_sync(0xffffffffu, s, o);
    float mu = s * (1.0f / 256.0f);
    float d0x = v0.x - mu, d0y = v0.y - mu, d0z = v0.z - mu, d0w = v0.w - mu;
    float d1x = v1.x - mu, d1y = v1.y - mu, d1z = v1.z - mu, d1w = v1.w - mu;
    float vs = d0x * d0x + d0y * d0y + d0z * d0z + d0w * d0w +
               d1x * d1x + d1y * d1y + d1z * d1z + d1w * d1w;
#pragma unroll
    for (int o = 16; o; o >>= 1) vs += __shfl_xor_sync(0xffffffffu, vs, o);
    float rs = rsqrtf(vs * (1.0f / 256.0f) + 1e-5f);
    const float4* gp = (const float4*)gamma;
    const float4* bp = (const float4*)beta;
    float4 gm0 = gp[lane * 2], gm1 = gp[lane * 2 + 1];
    float4 bt0 = bp[lane * 2], bt1 = bp[lane * 2 + 1];
    float4 o0 = make_float4(gm0.x * d0x * rs + bt0.x, gm0.y * d0y * rs + bt0.y,
                            gm0.z * d0z * rs + bt0.z, gm0.w * d0w * rs + bt0.w);
    float4 o1 = make_float4(gm1.x * d1x * rs + bt1.x, gm1.y * d1y * rs + bt1.y,
                            gm1.z * d1z * rs + bt1.z, gm1.w * d1w * rs + bt1.w);
    float4* orow = (float4*)(out + (size_t)n * FOUT);
    orow[lane * 2]     = o0;
    orow[lane * 2 + 1] = o1;
}

// ---------------- launch ----------------
extern "C" void kernel_launch(void* const* d_in, const int* in_sizes, int n_in,
                              void* d_out, int out_size) {
    const float* x     = (const float*)d_in[0];
    const int*   adj   = (const int*)d_in[1];
    const float* W     = (const float*)d_in[2];
    const float* a     = (const float*)d_in[3];
    const float* gamma = (const float*)d_in[4];
    const float* beta  = (const float*)d_in[5];
    float* out = (float*)d_out;

    pack_adj_kernel<<<2048, 256>>>(adj);
    gemm_h_kernel<<<dim3(64, 4), 256>>>(x, W);
    prep_kernel<<<512, 256>>>(a);

    size_t shmem = 19456 * sizeof(float);   // 77824 B
    cudaFuncSetAttribute(attn_kernel, cudaFuncAttributeMaxDynamicSharedMemorySize,
                         (int)shmem);
    attn_kernel<<<dim3(64, 4), 256, shmem>>>();

    ln_kernel<<<512, 256>>>(gamma, beta, out);
}

// round 4
// speedup vs baseline: 1.1536x; 1.1536x over previous
#include <cuda_runtime.h>
#include <cuda_bf16.h>
#include <cstdint>

#define NN   4096
#define FIN  256
#define FOUT 256
#define NH   4
#define DD   64
#define ALPHA 0.2f

// ---------------- device scratch (no allocs allowed) ----------------
__device__ float    g_h [NN * FOUT];    // x@W, fp32 exact
__device__ float    g_hr[NN * FOUT];    // tf32-rounded copy (B operand)
__device__ unsigned g_adjbits[NN * (NN / 32)];   // 2 MB bitmask
__device__ float    g_A[NH * NN];       // exp(si)
__device__ float    g_B[NH * NN];       // exp(alpha*si)
__device__ float    g_T[NH * NN];       // exp(-si)
__device__ float2   g_e12[NH * NN];     // {exp(sj), exp(alpha*sj)}
__device__ float    g_att[NN * FOUT];   // attention output pre-LN

// ---------------- cp.async helpers ----------------
__device__ __forceinline__ void cp16(uint32_t dst, const void* src) {
    asm volatile("cp.async.cg.shared.global [%0], [%1], 16;\n" :: "r"(dst), "l"(src));
}
__device__ __forceinline__ void cp8(uint32_t dst, const void* src) {
    asm volatile("cp.async.ca.shared.global [%0], [%1], 8;\n" :: "r"(dst), "l"(src));
}
__device__ __forceinline__ void cp_commit() {
    asm volatile("cp.async.commit_group;\n");
}
__device__ __forceinline__ void cp_wait1() {
    asm volatile("cp.async.wait_group 1;\n");
}

// ---------------- kernel 1: pack adj int32 -> bits ----------------
__global__ void pack_adj_kernel(const int* __restrict__ adj) {
    int lane = threadIdx.x & 31;
    size_t gw = (size_t)(blockIdx.x * blockDim.x + threadIdx.x) >> 5;
    const int* base = adj + gw * 1024;
    unsigned myword = 0;
#pragma unroll
    for (int i = 0; i < 32; i++) {
        int v = base[i * 32 + lane];
        unsigned b = __ballot_sync(0xffffffffu, v > 0);
        if (lane == i) myword = b;
    }
    g_adjbits[gw * 32 + lane] = myword;
}

// ---------------- kernel 2: h = x @ W (fp32 SIMT tiled) ----------------
__global__ __launch_bounds__(256) void gemm_h_kernel(const float* __restrict__ x,
                                                     const float* __restrict__ W) {
    __shared__ float xsT[16][68];
    __shared__ float wsm[16][68];
    int t  = threadIdx.x;
    int m0 = blockIdx.x * 64;
    int n0 = blockIdx.y * 64;
    int r0 = (t >> 4) << 2;
    int c0 = (t & 15) << 2;
    float acc[4][4] = {};

    for (int kt = 0; kt < 16; kt++) {
        int k0 = kt * 16;
        {
            int row = t >> 2, c4 = t & 3;
            float4 v = *(const float4*)(x + (size_t)(m0 + row) * FIN + k0 + c4 * 4);
            xsT[c4 * 4 + 0][row] = v.x;
            xsT[c4 * 4 + 1][row] = v.y;
            xsT[c4 * 4 + 2][row] = v.z;
            xsT[c4 * 4 + 3][row] = v.w;
        }
        {
            int r = t >> 4, c4 = t & 15;
            *(float4*)&wsm[r][c4 * 4] =
                *(const float4*)(W + (size_t)(k0 + r) * FOUT + n0 + c4 * 4);
        }
        __syncthreads();
#pragma unroll
        for (int k = 0; k < 16; k++) {
            float4 av = *(float4*)&xsT[k][r0];
            float4 bv = *(float4*)&wsm[k][c0];
            acc[0][0] += av.x * bv.x; acc[0][1] += av.x * bv.y; acc[0][2] += av.x * bv.z; acc[0][3] += av.x * bv.w;
            acc[1][0] += av.y * bv.x; acc[1][1] += av.y * bv.y; acc[1][2] += av.y * bv.z; acc[1][3] += av.y * bv.w;
            acc[2][0] += av.z * bv.x; acc[2][1] += av.z * bv.y; acc[2][2] += av.z * bv.z; acc[2][3] += av.z * bv.w;
            acc[3][0] += av.w * bv.x; acc[3][1] += av.w * bv.y; acc[3][2] += av.w * bv.z; acc[3][3] += av.w * bv.w;
        }
        __syncthreads();
    }
#pragma unroll
    for (int i = 0; i < 4; i++) {
        size_t off = (size_t)(m0 + r0 + i) * FOUT + n0 + c0;
        float4 v = make_float4(acc[i][0], acc[i][1], acc[i][2], acc[i][3]);
        *(float4*)(g_h + off) = v;
        float4 vr;
        unsigned u;
        asm("cvt.rna.tf32.f32 %0, %1;" : "=r"(u) : "f"(v.x)); vr.x = __uint_as_float(u);
        asm("cvt.rna.tf32.f32 %0, %1;" : "=r"(u) : "f"(v.y)); vr.y = __uint_as_float(u);
        asm("cvt.rna.tf32.f32 %0, %1;" : "=r"(u) : "f"(v.z)); vr.z = __uint_as_float(u);
        asm("cvt.rna.tf32.f32 %0, %1;" : "=r"(u) : "f"(v.w)); vr.w = __uint_as_float(u);
        *(float4*)(g_hr + off) = vr;
    }
}

// ---------------- kernel 3: si/sj dots + exp tables ----------------
__global__ void prep_kernel(const float* __restrict__ a) {
    __shared__ float a_s[128];
    int t = threadIdx.x;
    if (t < 128) a_s[t] = a[t];
    __syncthreads();
    int wid  = t >> 5, lane = t & 31;
    int n    = blockIdx.x * 8 + wid;
    int head = lane >> 3;
    int sub  = lane & 7;
    const float4* hrow = (const float4*)(g_h + (size_t)n * FOUT);
    float psi = 0.f, psj = 0.f;
#pragma unroll
    for (int v = 0; v < 2; v++) {
        float4 hv = hrow[lane * 2 + v];
        int db = sub * 8 + v * 4;
        psi += hv.x * a_s[db]      + hv.y * a_s[db + 1]      + hv.z * a_s[db + 2]      + hv.w * a_s[db + 3];
        psj += hv.x * a_s[64 + db] + hv.y * a_s[64 + db + 1] + hv.z * a_s[64 + db + 2] + hv.w * a_s[64 + db + 3];
    }
#pragma unroll
    for (int off = 4; off; off >>= 1) {
        psi += __shfl_down_sync(0xffffffffu, psi, off);
        psj += __shfl_down_sync(0xffffffffu, psj, off);
    }
    if (sub == 0) {
        int idx = head * NN + n;
        g_A[idx]   = expf(psi);
        g_B[idx]   = expf(ALPHA * psi);
        g_T[idx]   = expf(-psi);
        g_e12[idx] = make_float2(expf(psj), expf(ALPHA * psj));
    }
}

// ---------------- kernel 4: fused attention (tf32 mma.sync) ----------------
__device__ __forceinline__ void mma_tf32(float* d, unsigned a0, unsigned a1, unsigned a2,
                                         unsigned a3, unsigned b0, unsigned b1) {
    asm volatile(
        "mma.sync.aligned.m16n8k8.row.col.f32.tf32.tf32.f32 "
        "{%0,%1,%2,%3}, {%4,%5,%6,%7}, {%8,%9}, {%0,%1,%2,%3};\n"
        : "+f"(d[0]), "+f"(d[1]), "+f"(d[2]), "+f"(d[3])
        : "r"(a0), "r"(a1), "r"(a2), "r"(a3), "r"(b0), "r"(b1));
}

// smem float offsets
#define OFF_HS   0        // [2][64*72]  = 9216
#define OFF_WS   9216     // [64*72]     = 4608
#define OFF_E12  13824    // float2[2][64] = 256 floats
#define OFF_ADJ  14080    // unsigned[2][128] = 256
#define OFF_AS   14336    // 64
#define OFF_BS   14400
#define OFF_TS   14464
#define OFF_SP   14528    // 256
#define OFF_SSM  14784    // 64
#define SMEM_FLOATS 14848 // 59392 bytes

// block: 64 n-rows x 1 head, loops m in tiles of 64.  grid (64, 4), 256 thr, 3 CTA/SM.
__global__ __launch_bounds__(256, 3) void attn_kernel() {
    extern __shared__ float sm[];
    float*    Ws   = sm + OFF_WS;
    float2*   e12b = (float2*)(sm + OFF_E12);    // [2][64]
    unsigned* adjb = (unsigned*)(sm + OFF_ADJ);  // [2][128]
    float*    As   = sm + OFF_AS;
    float*    Bs   = sm + OFF_BS;
    float*    Ts   = sm + OFF_TS;
    float*    Sp   = sm + OFF_SP;
    float*    Ssm  = sm + OFF_SSM;

    int t  = threadIdx.x;
    int hd = blockIdx.y;
    int n0 = blockIdx.x * 64;

    uint32_t smem_b = (uint32_t)__cvta_generic_to_shared(sm);
    uint32_t hs_b   = smem_b;                      // byte base of Hs[0]
    uint32_t e12_b  = smem_b + OFF_E12 * 4;
    uint32_t adj_b  = smem_b + OFF_ADJ * 4;

    if (t < 64) {
        As[t] = g_A[hd * NN + n0 + t];
        Bs[t] = g_B[hd * NN + n0 + t];
        Ts[t] = g_T[hd * NN + n0 + t];
    }

    int nl = t & 63, mc = t >> 6;      // w-gen role: n=nl, m strip mc*16..+15
    int lane = t & 31, wid = t >> 5;
    int g   = lane >> 2;               // group-of-4 id (row in frag)
    int tig = lane & 3;                // thread-in-group
    int wn0 = (wid & 3) * 16;          // warp n offset
    int wd0 = (wid >> 2) * 32;         // warp d offset
    float acc[4][4] = {};
    float sacc = 0.f;

    // stage tile mt into buffer b (cp.async)
    auto stage = [&](int mt, int b) {
        int m0 = mt * 64;
        uint32_t hb = hs_b + (uint32_t)b * 4608u * 4u;
#pragma unroll
        for (int r = 0; r < 4; r++) {
            int li = t + r * 256;
            int mi = li >> 4, d4 = li & 15;
            cp16(hb + (uint32_t)(mi * 72 + d4 * 4) * 4u,
                 g_hr + (size_t)(m0 + mi) * FOUT + hd * DD + d4 * 4);
        }
        if (t < 32)
            cp16(e12_b + (uint32_t)b * 512u + (uint32_t)t * 16u,
                 (const char*)(g_e12 + hd * NN + m0) + t * 16);
        if (t >= 64 && t < 128) {
            int rr = t - 64;
            cp8(adj_b + (uint32_t)b * 512u + (uint32_t)rr * 8u,
                g_adjbits + (size_t)(n0 + rr) * (NN / 32) + mt * 2);
        }
    };

    stage(0, 0);
    cp_commit();

    for (int mt = 0; mt < NN / 64; mt++) {
        int p = mt & 1;
        if (mt < NN / 64 - 1) stage(mt + 1, p ^ 1);
        cp_commit();
        cp_wait1();
        __syncthreads();   // staged data visible; also orders prev mma before Ws overwrite

        // ---- w-gen: 16 elements per thread (rounded to tf32, RNA) ----
        float An = As[nl], Bn = Bs[nl], Tn = Ts[nl];
        const float2* e12 = e12b + p * 64;
        unsigned word = adjb[p * 128 + nl * 2 + (mc >> 1)] >> ((mc & 1) * 16);
#pragma unroll
        for (int i = 0; i < 16; i++) {
            float2 e = e12[mc * 16 + i];
            float wv = (e.x > Tn) ? (An * e.x) : (Bn * e.y);
            wv = ((word >> i) & 1u) ? wv : 0.f;
            unsigned wt;
            asm("cvt.rna.tf32.f32 %0, %1;" : "=r"(wt) : "f"(wv));
            float wr = __uint_as_float(wt);
            sacc += wr;                      // denominator from SAME rounded value
            Ws[(mc * 16 + i) * 72 + nl] = wr;
        }
        __syncthreads();

        // ---- mma: C(64x64) += W(64n x 64m) * H(64m x 64d), 8 k-steps ----
        const float* H = sm + p * 4608;
#pragma unroll
        for (int ks = 0; ks < 8; ks++) {
            int k0 = ks * 8;
            unsigned a0 = __float_as_uint(Ws[(k0 + tig) * 72 + wn0 + g]);
            unsigned a1 = __float_as_uint(Ws[(k0 + tig) * 72 + wn0 + g + 8]);
            unsigned a2 = __float_as_uint(Ws[(k0 + tig + 4) * 72 + wn0 + g]);
            unsigned a3 = __float_as_uint(Ws[(k0 + tig + 4) * 72 + wn0 + g + 8]);
#pragma unroll
            for (int j = 0; j < 4; j++) {
                unsigned b0 = __float_as_uint(H[(k0 + tig) * 72 + wd0 + 8 * j + g]);
                unsigned b1 = __float_as_uint(H[(k0 + tig + 4) * 72 + wd0 + 8 * j + g]);
                mma_tf32(acc[j], a0, a1, a2, a3, b0, b1);
            }
        }
    }

    // softmax denominator reduction (w-gen thread (nl,mc) holds partial over its strips)
    Sp[t] = sacc;
    __syncthreads();
    if (t < 64) Ssm[t] = Sp[t] + Sp[64 + t] + Sp[128 + t] + Sp[192 + t];
    __syncthreads();

    float inv0 = 1.0f / Ssm[wn0 + g];
    float inv1 = 1.0f / Ssm[wn0 + g + 8];
    int na = n0 + wn0 + g, nb = na + 8;
    int colbase = hd * DD + wd0 + 2 * tig;
#pragma unroll
    for (int j = 0; j < 4; j++) {
        int col = colbase + 8 * j;
        g_att[(size_t)na * FOUT + col]     = acc[j][0] * inv0;
        g_att[(size_t)na * FOUT + col + 1] = acc[j][1] * inv0;
        g_att[(size_t)nb * FOUT + col]     = acc[j][2] * inv1;
        g_att[(size_t)nb * FOUT + col + 1] = acc[j][3] * inv1;
    }
}

// ---------------- kernel 5: LayerNorm ----------------
__global__ void ln_kernel(const float* __restrict__ gamma,
                          const float* __restrict__ beta,
                          float* __restrict__ out) {
    int wid = threadIdx.x >> 5, lane = threadIdx.x & 31;
    int n = blockIdx.x * 8 + wid;
    const float4* row = (const float4*)(g_att + (size_t)n * FOUT);
    float4 v0 = row[lane * 2], v1 = row[lane * 2 + 1];
    float s = v0.x + v0.y + v0.z + v0.w + v1.x + v1.y + v1.z + v1.w;
#pragma unroll
    for (int o = 16; o; o >>= 1) s += __shfl_xor_sync(0xffffffffu, s, o);
    float mu = s * (1.0f / 256.0f);
    float d0x = v0.x - mu, d0y = v0.y - mu, d0z = v0.z - mu, d0w = v0.w - mu;
    float d1x = v1.x - mu, d1y = v1.y - mu, d1z = v1.z - mu, d1w = v1.w - mu;
    float vs = d0x * d0x + d0y * d0y + d0z * d0z + d0w * d0w +
               d1x * d1x + d1y * d1y + d1z * d1z + d1w * d1w;
#pragma unroll
    for (int o = 16; o; o >>= 1) vs += __shfl_xor_sync(0xffffffffu, vs, o);
    float rs = rsqrtf(vs * (1.0f / 256.0f) + 1e-5f);
    const float4* gp = (const float4*)gamma;
    const float4* bp = (const float4*)beta;
    float4 gm0 = gp[lane * 2], gm1 = gp[lane * 2 + 1];
    float4 bt0 = bp[lane * 2], bt1 = bp[lane * 2 + 1];
    float4 o0 = make_float4(gm0.x * d0x * rs + bt0.x, gm0.y * d0y * rs + bt0.y,
                            gm0.z * d0z * rs + bt0.z, gm0.w * d0w * rs + bt0.w);
    float4 o1 = make_float4(gm1.x * d1x * rs + bt1.x, gm1.y * d1y * rs + bt1.y,
                            gm1.z * d1z * rs + bt1.z, gm1.w * d1w * rs + bt1.w);
    float4* orow = (float4*)(out + (size_t)n * FOUT);
    orow[lane * 2]     = o0;
    orow[lane * 2 + 1] = o1;
}

// ---------------- launch ----------------
extern "C" void kernel_launch(void* const* d_in, const int* in_sizes, int n_in,
                              void* d_out, int out_size) {
    const float* x     = (const float*)d_in[0];
    const int*   adj   = (const int*)d_in[1];
    const float* W     = (const float*)d_in[2];
    const float* a     = (const float*)d_in[3];
    const float* gamma = (const float*)d_in[4];
    const float* beta  = (const float*)d_in[5];
    float* out = (float*)d_out;

    pack_adj_kernel<<<2048, 256>>>(adj);
    gemm_h_kernel<<<dim3(64, 4), 256>>>(x, W);
    prep_kernel<<<512, 256>>>(a);

    size_t shmem = SMEM_FLOATS * sizeof(float);   // 59392 B
    cudaFuncSetAttribute(attn_kernel, cudaFuncAttributeMaxDynamicSharedMemorySize,
                         (int)shmem);
    attn_kernel<<<dim3(64, 4), 256, shmem>>>();

    ln_kernel<<<512, 256>>>(gamma, beta, out);
}